// round 5
// baseline (speedup 1.0000x reference)
#include <cuda_runtime.h>

// Problem shape (fixed by setup_inputs): x: (B=4, S=4096, D=64) float32
// out: (B, S) float32
#define S_LEN  4096
#define D_DIM  64
#define CH     8               // chunk size (norm elements per L1 entry)
#define NCH    (S_LEN / CH)    // 512 chunks per row

// Scratch (device globals, no allocation):
__device__ float g_norms[4 * S_LEN];       // per-(b,t) L1 norms
__device__ float g_L1[4 * NCH];            // 8-element chunk minima

// ---------------------------------------------------------------------------
// Kernel 1: norms[row] = sum_d |x[row,d]|, PLUS the 8-row chunk min.
// Block = 256 threads = 8 warps = 8 consecutive rows = exactly one chunk.
// ---------------------------------------------------------------------------
__global__ void norms_kernel(const float* __restrict__ x) {
    __shared__ float swarp[8];

    const int warp = threadIdx.x >> 5;
    const int lane = threadIdx.x & 31;
    const int row  = blockIdx.x * 8 + warp;

    const float2 v = reinterpret_cast<const float2*>(x + (size_t)row * D_DIM)[lane];
    float s = fabsf(v.x) + fabsf(v.y);
#pragma unroll
    for (int o = 16; o > 0; o >>= 1)
        s += __shfl_xor_sync(0xffffffffu, s, o);

    if (lane == 0) {
        g_norms[row] = s;
        swarp[warp] = s;
    }
    __syncthreads();

    if (threadIdx.x == 0) {
        float m = swarp[0];
#pragma unroll
        for (int i = 1; i < 8; i++) m = fminf(m, swarp[i]);
        g_L1[blockIdx.x] = m;   // global chunk index == blockIdx.x
    }
}

// ---------------------------------------------------------------------------
// Kernel 2: thread-per-query nearest-crossing search, 7-ary descend.
// For each (b,t): nearest j < t with norms[j] < 0.7*(norms[t]+eps);
// answer t - j, else 0.
//
// smem: norms row (16KB) + window-min tables at chunk scales 1/8/64 (2KB ea).
//   L8[c]  = min over chunks [c, c+8)
//   L64[c] = min over chunks [c, c+64)
// Query: (A) partial chunk scan (<=7 predicated LDS), (B) descend scales
// {64, 8, 1}, each probing up to 7 independent steps (one LDS round each),
// (C) scan the guaranteed-dirty chunk pos-1 (8 predicated LDS).
// Only 3 __syncthreads total.
// ---------------------------------------------------------------------------
#define QPB 256

__device__ __forceinline__ int leading_clean7(const float* __restrict__ tab,
                                              int pos, int s, float thr) {
    // Max m in [0,7] s.t. ranges [pos-k*s, pos-(k-1)*s) are clean for k<=m.
    bool ok = true;
    int m = 0;
#pragma unroll
    for (int k = 1; k <= 7; k++) {
        const int npos = pos - k * s;
        const float v = tab[npos >= 0 ? npos : 0];   // loads independent
        ok = ok && (npos >= 0) && (v >= thr);
        m += ok ? 1 : 0;
    }
    return m;
}

__global__ void scan_kernel(float* __restrict__ out) {
    __shared__ float sn[S_LEN];      // 16 KB
    __shared__ float sL1[NCH];       // 2 KB
    __shared__ float sL8[NCH];       // 2 KB
    __shared__ float sL64[NCH];      // 2 KB

    const int b   = blockIdx.y;
    const int tid = threadIdx.x;

    // Concurrent coalesced loads: norms row (float4) + L1 chunk minima.
    const float4* srcN = reinterpret_cast<const float4*>(g_norms + (size_t)b * S_LEN);
#pragma unroll
    for (int i = 0; i < (S_LEN / 4) / QPB; i++)
        reinterpret_cast<float4*>(sn)[tid + i * QPB] = srcN[tid + i * QPB];
    if (tid < NCH / 4)
        reinterpret_cast<float4*>(sL1)[tid] =
            reinterpret_cast<const float4*>(g_L1 + (size_t)b * NCH)[tid];
    __syncthreads();

    // Build L8 (window min over 8 L1 entries). 2 entries/thread.
#pragma unroll
    for (int i = 0; i < NCH / QPB; i++) {
        const int c = tid + i * QPB;
        float m = sL1[c];
#pragma unroll
        for (int k = 1; k < 8; k++) {
            const int idx = c + k;
            m = fminf(m, sL1[idx < NCH ? idx : NCH - 1]);
        }
        sL8[c] = m;
    }
    __syncthreads();

    // Build L64 (window min over 64 chunks = 8 L8 entries, stride 8).
#pragma unroll
    for (int i = 0; i < NCH / QPB; i++) {
        const int c = tid + i * QPB;
        float m = sL8[c];
#pragma unroll
        for (int k = 1; k < 8; k++) {
            const int idx = c + k * 8;
            m = fminf(m, sL8[idx < NCH ? idx : NCH - 1]);
        }
        sL64[c] = m;
    }
    __syncthreads();

    // ----- per-thread query -----
    const int t = blockIdx.x * QPB + tid;
    const float thr = 0.7f * (sn[t] + 1e-8f);

    // A) partial chunk [cb, t)
    const int cb = t & ~(CH - 1);
    int best = -1;
#pragma unroll
    for (int k = 0; k < CH - 1; k++) {
        const int j = cb + k;
        if (j < t && sn[j] < thr) best = j;   // ascending k keeps max j
    }

    // B)+C) full chunks below
    if (best < 0 && cb > 0) {
        int pos = cb >> 3;                       // in [1, 511]
        pos -= 64 * leading_clean7(sL64, pos, 64, thr);
        pos -= 8  * leading_clean7(sL8,  pos, 8,  thr);
        pos -=      leading_clean7(sL1,  pos, 1,  thr);
        if (pos > 0) {
            const int base = (pos - 1) * CH;     // guaranteed-dirty chunk
#pragma unroll
            for (int k = 0; k < CH; k++)
                if (sn[base + k] < thr) best = base + k;
        }
    }

    out[(size_t)b * S_LEN + t] = best >= 0 ? (float)(t - best) : 0.0f;
}

// ---------------------------------------------------------------------------
// Launch
// ---------------------------------------------------------------------------
extern "C" void kernel_launch(void* const* d_in, const int* in_sizes, int n_in,
                              void* d_out, int out_size) {
    const float* x = (const float*)d_in[0];
    float* out = (float*)d_out;

    const int n_rows = out_size;          // B * S = 16384
    const int B = n_rows / S_LEN;         // 4

    // Kernel 1: 8 rows (one chunk) per 256-thread block.
    norms_kernel<<<n_rows / 8, 256>>>(x);

    // Kernel 2: 256 queries per block, grid (16, B).
    dim3 grid(S_LEN / QPB, B);
    scan_kernel<<<grid, QPB>>>(out);
}

// round 6
// speedup vs baseline: 1.0037x; 1.0037x over previous
#include <cuda_runtime.h>

// Problem shape (fixed by setup_inputs): x: (B=4, S=4096, D=64) f32; out: (B,S) f32
#define S_LEN  4096
#define D_DIM  64
#define CH     8               // chunk size (norm elements per L1 entry)
#define NCH    (S_LEN / CH)    // 512 chunks per row
#define NB     128             // grid size (all blocks co-resident: 128 <= 148 SMs)
#define ROWS_PER_BLK (4 * S_LEN / NB)   // 128 rows per block in phase 1
#define QPB    128             // queries per block in phase 2 (32 blocks per batch row)

// Device-global scratch (no allocation):
__device__ float    g_norms[4 * S_LEN];
__device__ unsigned g_bar;     // monotonic grid-barrier counter (never reset;
                               // each launch adds exactly NB, generations inferred)

// Max m in [0,7] s.t. windows [pos-k*s, pos-(k-1)*s) are all clean for k<=m.
// tab[c] = min over s chunks starting at c. Loads are independent (pipelined).
__device__ __forceinline__ int leading_clean7(const float* __restrict__ tab,
                                              int pos, int s, float thr) {
    bool ok = true;
    int m = 0;
#pragma unroll
    for (int k = 1; k <= 7; k++) {
        const int npos = pos - k * s;
        const float v = tab[npos >= 0 ? npos : 0];
        ok = ok && (npos >= 0) && (v >= thr);
        m += ok ? 1 : 0;
    }
    return m;
}

__device__ __forceinline__ float min8(float4 a, float4 b) {
    return fminf(fminf(fminf(a.x, a.y), fminf(a.z, a.w)),
                 fminf(fminf(b.x, b.y), fminf(b.z, b.w)));
}

__global__ void __launch_bounds__(256, 1) fused_kernel(const float* __restrict__ x,
                                                       float* __restrict__ out) {
    __shared__ float sn[S_LEN];      // 16 KB norms row
    __shared__ float sL1[NCH];       // 2 KB: min over 1 chunk  (8 elems)
    __shared__ float sL8[NCH];       // 2 KB: min over 8 chunks (64 elems)
    __shared__ float sL64[NCH];      // 2 KB: min over 64 chunks (512 elems)

    const int tid  = threadIdx.x;
    const int warp = tid >> 5;
    const int lane = tid & 31;

    // ---------- Phase 1: norms for this block's 128 rows ----------
    // Half-warp per row: 16 lanes x float4 = 64 floats (256B, coalesced).
#pragma unroll
    for (int i = 0; i < ROWS_PER_BLK / 16; i++) {
        const int row = blockIdx.x * ROWS_PER_BLK + i * 16 + warp * 2 + (lane >> 4);
        const float4 v = reinterpret_cast<const float4*>(x + (size_t)row * D_DIM)[lane & 15];
        float s = fabsf(v.x) + fabsf(v.y) + fabsf(v.z) + fabsf(v.w);
        s += __shfl_xor_sync(0xffffffffu, s, 8);
        s += __shfl_xor_sync(0xffffffffu, s, 4);
        s += __shfl_xor_sync(0xffffffffu, s, 2);
        s += __shfl_xor_sync(0xffffffffu, s, 1);
        if ((lane & 15) == 0) g_norms[row] = s;
    }

    // ---------- Software grid barrier (monotonic, replay-safe) ----------
    __threadfence();         // make g_norms stores visible device-wide
    __syncthreads();         // all warps of this block arrived
    if (tid == 0) {
        const unsigned my = atomicAdd(&g_bar, 1u) + 1u;
        const unsigned target = (my + NB - 1u) / NB * NB;  // end of this generation
        while (atomicAdd(&g_bar, 0u) < target) { }
        __threadfence();
    }
    __syncthreads();

    // ---------- Phase 2: load row + build tables ----------
    const int b     = blockIdx.x >> 5;            // 32 blocks per batch row
    const int tbase = (blockIdx.x & 31) * QPB;

    // Thread tid loads 16 contiguous floats (4x float4) = exactly chunks
    // 2*tid and 2*tid+1 -> level-0 minima computed in registers, no extra barrier.
    {
        const float4* srcN = reinterpret_cast<const float4*>(g_norms + (size_t)b * S_LEN);
        const float4 a0 = srcN[4 * tid + 0];
        const float4 a1 = srcN[4 * tid + 1];
        const float4 a2 = srcN[4 * tid + 2];
        const float4 a3 = srcN[4 * tid + 3];
        float4* dst = reinterpret_cast<float4*>(sn);
        dst[4 * tid + 0] = a0;
        dst[4 * tid + 1] = a1;
        dst[4 * tid + 2] = a2;
        dst[4 * tid + 3] = a3;
        sL1[2 * tid + 0] = min8(a0, a1);
        sL1[2 * tid + 1] = min8(a2, a3);
    }
    __syncthreads();

    // L8: window min over 8 L1 entries (clamped reads only touch unused tail).
#pragma unroll
    for (int i = 0; i < NCH / 256; i++) {
        const int c = tid + i * 256;
        float m = sL1[c];
#pragma unroll
        for (int k = 1; k < 8; k++) {
            const int idx = c + k;
            m = fminf(m, sL1[idx < NCH ? idx : NCH - 1]);
        }
        sL8[c] = m;
    }
    __syncthreads();

    // L64: window min over 64 chunks = 8 L8 entries at stride 8.
#pragma unroll
    for (int i = 0; i < NCH / 256; i++) {
        const int c = tid + i * 256;
        float m = sL8[c];
#pragma unroll
        for (int k = 1; k < 8; k++) {
            const int idx = c + k * 8;
            m = fminf(m, sL8[idx < NCH ? idx : NCH - 1]);
        }
        sL64[c] = m;
    }
    __syncthreads();

    // ---------- Phase 3: one query per thread (tid < QPB) ----------
    if (tid < QPB) {
        const int t = tbase + tid;
        const float thr = 0.7f * (sn[t] + 1e-8f);

        // A) partial chunk [cb, t): predicated scan, ascending keeps max j.
        const int cb = t & ~(CH - 1);
        int best = -1;
#pragma unroll
        for (int k = 0; k < CH - 1; k++) {
            const int j = cb + k;
            if (j < t && sn[j] < thr) best = j;
        }

        // B) 7-ary descend over scales {64, 8, 1}; C) scan dirty chunk pos-1.
        if (best < 0 && cb > 0) {
            int pos = cb >> 3;                       // in [1, 511]
            pos -= 64 * leading_clean7(sL64, pos, 64, thr);
            pos -= 8  * leading_clean7(sL8,  pos, 8,  thr);
            pos -=      leading_clean7(sL1,  pos, 1,  thr);
            if (pos > 0) {
                const int base = (pos - 1) * CH;
#pragma unroll
                for (int k = 0; k < CH; k++)
                    if (sn[base + k] < thr) best = base + k;
            }
        }

        out[(size_t)b * S_LEN + t] = best >= 0 ? (float)(t - best) : 0.0f;
    }
}

// ---------------------------------------------------------------------------
// Launch: single fused kernel, 128 blocks x 256 threads.
// ---------------------------------------------------------------------------
extern "C" void kernel_launch(void* const* d_in, const int* in_sizes, int n_in,
                              void* d_out, int out_size) {
    const float* x = (const float*)d_in[0];
    float* out = (float*)d_out;
    fused_kernel<<<NB, 256>>>(x, out);
}